// round 1
// baseline (speedup 1.0000x reference)
#include <cuda_runtime.h>
#include <cuda_bf16.h>
#include <math.h>

// Problem dims
#define B_  64
#define N_  16
#define T_  64
#define D_  128
#define H_  256
#define M_  17          // N+1 slots
#define RALL 1088       // B + B*N batch rows
#define FLATR 69632     // RALL*T  (also B*M_*T_)

// Output offsets (concat of: out(4096), node_hT(16384), ngh_hT(262144), A(4456448))
#define OFF_OUT 0
#define OFF_NHT 4096
#define OFF_GHT 20480
#define OFF_A   282624
#define OUT_TOTAL 4739072

// ---------------- device scratch (no runtime allocation allowed) ----------------
__device__ float g_gi[(size_t)FLATR * 768];      // precomputed x@Wih.T, [(r*T+t)*768+j]
__device__ float g_h0[RALL * H_];                // ping-pong hidden state
__device__ float g_h1[RALL * H_];
__device__ float g_hall[(size_t)FLATR * H_];     // kv layout [((b*17+m)*64+t)*256+h]
__device__ float g_nodeout[(size_t)B_ * T_ * H_];// [(b*64+t)*256+h]
__device__ float g_Q2[(size_t)B_ * T_ * H_];
__device__ float g_tmp[H_ * H_];                 // Wq^T @ Wbil
__device__ float g_WfullT[H_ * H_];              // (Wq^T Wbil Wk) transposed for A@B^T GEMM
__device__ float g_wvc[H_];                      // Wprj @ Wv
__device__ float g_vp[FLATR];                    // hall . wvc
__device__ float g_po[B_ * M_ * T_];             // per-slot partial output

// ---------------- prep kernels ----------------
__global__ void prep_tmp(const float* __restrict__ Wq, const float* __restrict__ Wbil,
                         float* __restrict__ tmp) {
    int k = blockIdx.x, c = threadIdx.x;
    float s = 0.f;
    for (int a = 0; a < H_; a++) s += Wq[a * H_ + k] * Wbil[a * H_ + c];
    tmp[k * H_ + c] = s;
}

__global__ void prep_wfull(const float* __restrict__ tmp, const float* __restrict__ Wk,
                           float* __restrict__ WfullT) {
    int k = blockIdx.x, hp = threadIdx.x;
    float s = 0.f;
    for (int c = 0; c < H_; c++) s += tmp[k * H_ + c] * Wk[c * H_ + hp];
    WfullT[hp * H_ + k] = s;   // transposed store
}

__global__ void prep_wvc(const float* __restrict__ Wprj, const float* __restrict__ Wv,
                         float* __restrict__ wvc) {
    int hp = threadIdx.x;
    float s = 0.f;
    for (int h = 0; h < H_; h++) s += Wprj[h] * Wv[h * H_ + hp];
    wvc[hp] = s;
}

__global__ void init_h(const float* __restrict__ node_hidden,
                       const float* __restrict__ ngh_hidden,
                       float* __restrict__ h) {
    int row = blockIdx.x, u = threadIdx.x;
    float v = (row < B_) ? node_hidden[row * H_ + u]
                         : ngh_hidden[(row - B_) * H_ + u];
    h[row * H_ + u] = v;
}

// ---------------- generic fp32 GEMM: C[MxN] = A[MxK] @ B[NxK]^T ----------------
// requires M%128==0, N%128==0, K%8==0
__global__ __launch_bounds__(256) void sgemm128(const float* __restrict__ A,
                                                const float* __restrict__ B,
                                                float* __restrict__ C,
                                                int M, int N, int K) {
    __shared__ float As[8][128];
    __shared__ float Bs[8][128];
    int tid = threadIdx.x;
    int tx = tid & 15, ty = tid >> 4;
    int m0 = blockIdx.y * 128, n0 = blockIdx.x * 128;
    float acc[8][8] = {};
    for (int k0 = 0; k0 < K; k0 += 8) {
        #pragma unroll
        for (int i = 0; i < 4; i++) {
            int idx = tid + i * 256;
            int r = idx >> 3, c = idx & 7;
            As[c][r] = A[(size_t)(m0 + r) * K + k0 + c];
            Bs[c][r] = B[(size_t)(n0 + r) * K + k0 + c];
        }
        __syncthreads();
        #pragma unroll
        for (int k = 0; k < 8; k++) {
            float a[8], bv[8];
            #pragma unroll
            for (int i = 0; i < 8; i++) a[i] = As[k][ty * 8 + i];
            #pragma unroll
            for (int j = 0; j < 8; j++) bv[j] = Bs[k][tx * 8 + j];
            #pragma unroll
            for (int i = 0; i < 8; i++)
                #pragma unroll
                for (int j = 0; j < 8; j++) acc[i][j] += a[i] * bv[j];
        }
        __syncthreads();
    }
    #pragma unroll
    for (int i = 0; i < 8; i++)
        #pragma unroll
        for (int j = 0; j < 8; j++)
            C[(size_t)(m0 + ty * 8 + i) * N + n0 + tx * 8 + j] = acc[i][j];
}

// ---------------- GRU recurrent step (fused GEMM + gates) ----------------
// grid (17, 8): x = 64-row tile (block 0 == node rows exactly), y = 32-unit tile
__global__ __launch_bounds__(256) void gru_step(
    const float* __restrict__ hcur, float* __restrict__ hnext,
    const float* __restrict__ gi,
    const float* __restrict__ Whh_node, const float* __restrict__ Whh_ngh,
    const float* __restrict__ bih_node, const float* __restrict__ bhh_node,
    const float* __restrict__ bih_ngh,  const float* __restrict__ bhh_ngh,
    float* __restrict__ hall, float* __restrict__ nodeout, int t)
{
    __shared__ float Hs[16][64];
    __shared__ float Ws[16][96];
    int tid = threadIdx.x;
    int u  = tid & 31;     // unit within tile
    int rg = tid >> 5;     // row group 0..7 (== warp id -> Hs reads broadcast)
    int r0 = blockIdx.x * 64;
    int j0 = blockIdx.y * 32;
    bool is_node = (blockIdx.x == 0);
    const float* Whh = is_node ? Whh_node : Whh_ngh;

    float acc[8][3] = {};
    for (int k0 = 0; k0 < H_; k0 += 16) {
        for (int i = tid; i < 1024; i += 256) {
            int r = i >> 4, c = i & 15;
            Hs[c][r] = hcur[(size_t)(r0 + r) * H_ + k0 + c];
        }
        for (int i = tid; i < 1536; i += 256) {
            int gr = i >> 4, c = i & 15;
            int g = gr >> 5, uu = gr & 31;
            Ws[c][gr] = Whh[(size_t)(g * H_ + j0 + uu) * H_ + k0 + c];
        }
        __syncthreads();
        #pragma unroll
        for (int k = 0; k < 16; k++) {
            float wr = Ws[k][u], wz = Ws[k][32 + u], wn = Ws[k][64 + u];
            #pragma unroll
            for (int rr = 0; rr < 8; rr++) {
                float a = Hs[k][rg * 8 + rr];
                acc[rr][0] += a * wr;
                acc[rr][1] += a * wz;
                acc[rr][2] += a * wn;
            }
        }
        __syncthreads();
    }

    int j = j0 + u;
    const float* bih = is_node ? bih_node : bih_ngh;
    const float* bhh = is_node ? bhh_node : bhh_ngh;
    float bir = bih[j], biz = bih[256 + j], bin = bih[512 + j];
    float bhr = bhh[j], bhz = bhh[256 + j], bhn = bhh[512 + j];

    #pragma unroll
    for (int rr = 0; rr < 8; rr++) {
        int row = r0 + rg * 8 + rr;
        size_t gbase = ((size_t)row * T_ + t) * 768;
        float gir = gi[gbase + j]       + bir;
        float giz = gi[gbase + 256 + j] + biz;
        float gin = gi[gbase + 512 + j] + bin;
        float ghr = acc[rr][0] + bhr;
        float ghz = acc[rr][1] + bhz;
        float ghn = acc[rr][2] + bhn;
        float r = 1.f / (1.f + expf(-(gir + ghr)));
        float z = 1.f / (1.f + expf(-(giz + ghz)));
        float n = tanhf(gin + r * ghn);
        float hp = hcur[(size_t)row * H_ + j];
        float hnew = (1.f - z) * n + z * hp;
        hnext[(size_t)row * H_ + j] = hnew;
        int b, m;
        if (row < B_) { b = row; m = 0; }
        else { int q = row - B_; b = q >> 4; m = (q & 15) + 1; }
        hall[(((size_t)b * M_ + m) * T_ + t) * H_ + j] = hnew;
        if (row < B_) nodeout[((size_t)row * T_ + t) * H_ + j] = hnew;
    }
}

// ---------------- vproj: hall . wvc (warp per row) ----------------
__global__ void vproj_kernel(const float* __restrict__ hall, const float* __restrict__ wvc,
                             float* __restrict__ vp) {
    int warp = threadIdx.x >> 5, lane = threadIdx.x & 31;
    int row = blockIdx.x * 8 + warp;
    const float* hrow = hall + (size_t)row * H_;
    float s = 0.f;
    #pragma unroll
    for (int i = 0; i < 8; i++) s += hrow[lane + i * 32] * wvc[lane + i * 32];
    #pragma unroll
    for (int o = 16; o; o >>= 1) s += __shfl_xor_sync(0xffffffffu, s, o);
    if (lane == 0) vp[row] = s;
}

// ---------------- fused attention: S -> mask -> softmax -> A out + A@vproj ----------------
// one block per (b, m)
__global__ __launch_bounds__(256) void attn_kernel(
    const float* __restrict__ Q2, const float* __restrict__ hall,
    const float* __restrict__ vp, const float* __restrict__ bbil,
    float* __restrict__ A_out, float* __restrict__ po)
{
    __shared__ float Qs[16][64];
    __shared__ float Ks[16][64];
    __shared__ float Ssm[64 * 65];
    __shared__ float vps[64];
    __shared__ float bb[64];

    int bm = blockIdx.x;
    int b = bm / M_;
    int tid = threadIdx.x;
    const float* qsrc = Q2 + (size_t)b * T_ * H_;
    const float* ksrc = hall + (size_t)bm * T_ * H_;
    if (tid < 64) { vps[tid] = vp[bm * 64 + tid]; bb[tid] = bbil[tid]; }

    int tx = tid & 15, ty = tid >> 4;
    float acc[4][4] = {};
    for (int k0 = 0; k0 < H_; k0 += 16) {
        #pragma unroll
        for (int i = 0; i < 4; i++) {
            int idx = tid + i * 256;
            int r = idx >> 4, c = idx & 15;
            Qs[c][r] = qsrc[r * H_ + k0 + c];
            Ks[c][r] = ksrc[r * H_ + k0 + c];
        }
        __syncthreads();
        #pragma unroll
        for (int k = 0; k < 16; k++) {
            float q[4], kv[4];
            #pragma unroll
            for (int i = 0; i < 4; i++) q[i]  = Qs[k][ty + 16 * i];
            #pragma unroll
            for (int j = 0; j < 4; j++) kv[j] = Ks[k][tx + 16 * j];
            #pragma unroll
            for (int i = 0; i < 4; i++)
                #pragma unroll
                for (int j = 0; j < 4; j++) acc[i][j] += q[i] * kv[j];
        }
        __syncthreads();
    }
    #pragma unroll
    for (int i = 0; i < 4; i++)
        #pragma unroll
        for (int j = 0; j < 4; j++)
            Ssm[(ty + 16 * i) * 65 + tx + 16 * j] = acc[i][j];
    __syncthreads();

    // softmax + A write + partial output; warp per row group
    int warp = tid >> 5, lane = tid & 31;
    for (int rr = 0; rr < 8; rr++) {
        int t = warp * 8 + rr;
        int s2 = lane + 32;
        bool v1ok = (lane <= t), v2ok = (s2 <= t);
        float v1 = v1ok ? Ssm[t * 65 + lane] + bb[lane] : -3.0e38f;
        float v2 = v2ok ? Ssm[t * 65 + s2]   + bb[s2]   : -3.0e38f;
        float mx = fmaxf(v1, v2);
        #pragma unroll
        for (int o = 16; o; o >>= 1) mx = fmaxf(mx, __shfl_xor_sync(0xffffffffu, mx, o));
        float p1 = v1ok ? expf(v1 - mx) : 0.f;
        float p2 = v2ok ? expf(v2 - mx) : 0.f;
        float sum = p1 + p2;
        #pragma unroll
        for (int o = 16; o; o >>= 1) sum += __shfl_xor_sync(0xffffffffu, sum, o);
        float inv = 1.f / sum;
        float a1 = p1 * inv, a2 = p2 * inv;
        size_t abase = ((size_t)bm * 64 + t) * 64;
        A_out[abase + lane]      = a1;
        A_out[abase + lane + 32] = a2;
        float pv = a1 * vps[lane] + a2 * vps[s2];
        #pragma unroll
        for (int o = 16; o; o >>= 1) pv += __shfl_xor_sync(0xffffffffu, pv, o);
        if (lane == 0) po[bm * 64 + t] = pv;
    }
}

// ---------------- finalize: out reduce over slots + hT copies ----------------
__global__ void finalize(const float* __restrict__ po, const float* __restrict__ bprj,
                         const float* __restrict__ hfin, float* __restrict__ out) {
    int idx = blockIdx.x * 256 + threadIdx.x;
    if (idx < 4096) {
        int b = idx >> 6, t = idx & 63;
        float s = 17.f * bprj[0];
        #pragma unroll
        for (int m = 0; m < M_; m++) s += po[(b * M_ + m) * 64 + t];
        out[idx] = s;
    } else if (idx < OFF_GHT) {
        out[idx] = hfin[idx - OFF_NHT];               // node_hT (rows 0..63)
    } else if (idx < OFF_A) {
        out[idx] = hfin[B_ * H_ + (idx - OFF_GHT)];   // ngh_hT (rows 64..1087)
    }
}

// ---------------- launch ----------------
extern "C" void kernel_launch(void* const* d_in, const int* in_sizes, int n_in,
                              void* d_out, int out_size) {
    const float* node_input   = (const float*)d_in[0];
    const float* node_hidden  = (const float*)d_in[1];
    const float* ngh_input    = (const float*)d_in[2];
    const float* ngh_hidden   = (const float*)d_in[3];
    // d_in[4] = s_len (unused by reference)
    const float* Wih_node = (const float*)d_in[5];
    const float* Whh_node = (const float*)d_in[6];
    const float* bih_node = (const float*)d_in[7];
    const float* bhh_node = (const float*)d_in[8];
    const float* Wih_ngh  = (const float*)d_in[9];
    const float* Whh_ngh  = (const float*)d_in[10];
    const float* bih_ngh  = (const float*)d_in[11];
    const float* bhh_ngh  = (const float*)d_in[12];
    const float* Wq   = (const float*)d_in[13];
    const float* Wk   = (const float*)d_in[14];
    const float* Wv   = (const float*)d_in[15];
    const float* Wbil = (const float*)d_in[16];
    const float* bbil = (const float*)d_in[17];
    const float* Wprj = (const float*)d_in[18];
    const float* bprj = (const float*)d_in[19];
    float* out = (float*)d_out;

    float *gi, *h0, *h1, *hall, *nodeout, *Q2, *tmp, *WfullT, *wvc, *vpd, *pod;
    cudaGetSymbolAddress((void**)&gi, g_gi);
    cudaGetSymbolAddress((void**)&h0, g_h0);
    cudaGetSymbolAddress((void**)&h1, g_h1);
    cudaGetSymbolAddress((void**)&hall, g_hall);
    cudaGetSymbolAddress((void**)&nodeout, g_nodeout);
    cudaGetSymbolAddress((void**)&Q2, g_Q2);
    cudaGetSymbolAddress((void**)&tmp, g_tmp);
    cudaGetSymbolAddress((void**)&WfullT, g_WfullT);
    cudaGetSymbolAddress((void**)&wvc, g_wvc);
    cudaGetSymbolAddress((void**)&vpd, g_vp);
    cudaGetSymbolAddress((void**)&pod, g_po);

    // weight prep (tiny)
    prep_tmp<<<256, 256>>>(Wq, Wbil, tmp);
    prep_wfull<<<256, 256>>>(tmp, Wk, WfullT);
    prep_wvc<<<1, 256>>>(Wprj, Wv, wvc);
    init_h<<<RALL, 256>>>(node_hidden, ngh_hidden, h0);

    // hoisted input-side GRU GEMMs: gi = X @ Wih^T
    sgemm128<<<dim3(6, 32), 256>>>(node_input, Wih_node, gi, 4096, 768, 128);
    sgemm128<<<dim3(6, 512), 256>>>(ngh_input, Wih_ngh, gi + (size_t)4096 * 768, 65536, 768, 128);

    // sequential recurrence
    for (int t = 0; t < T_; t++) {
        const float* hc = (t & 1) ? h1 : h0;
        float* hn = (t & 1) ? h0 : h1;
        gru_step<<<dim3(17, 8), 256>>>(hc, hn, gi, Whh_node, Whh_ngh,
                                       bih_node, bhh_node, bih_ngh, bhh_ngh,
                                       hall, nodeout, t);
    }

    // attention
    sgemm128<<<dim3(2, 32), 256>>>(nodeout, WfullT, Q2, 4096, 256, 256);
    vproj_kernel<<<FLATR / 8, 256>>>(hall, wvc, vpd);
    attn_kernel<<<B_ * M_, 256>>>(Q2, hall, vpd, bbil, out + OFF_A, pod);

    finalize<<<(OFF_A + 255) / 256, 256>>>(pod, bprj, h0 /*T even -> final in h0*/, out);
}

// round 2
// speedup vs baseline: 2.5500x; 2.5500x over previous
#include <cuda_runtime.h>
#include <cuda_bf16.h>
#include <math.h>
#include <stdint.h>

// Problem dims
#define B_  64
#define N_  16
#define T_  64
#define D_  128
#define H_  256
#define M_  17          // N+1 slots
#define RALL 1088       // B + B*N batch rows
#define FLATR 69632     // RALL*T  (also B*M_*T_)

// Output offsets (concat of: out(4096), node_hT(16384), ngh_hT(262144), A(4456448))
#define OFF_OUT 0
#define OFF_NHT 4096
#define OFF_GHT 20480
#define OFF_A   282624

// ---------------- device scratch (no runtime allocation allowed) ----------------
__device__ float g_gi[(size_t)FLATR * 768];      // precomputed x@Wih.T, [(r*T+t)*768+j]
__device__ float g_h0[RALL * H_];                // ping-pong hidden state
__device__ float g_h1[RALL * H_];
__device__ float g_hall[(size_t)FLATR * H_];     // kv layout [((b*17+m)*64+t)*256+h]
__device__ float g_nodeout[(size_t)B_ * T_ * H_];// [(b*64+t)*256+h]
__device__ float g_Q2[(size_t)B_ * T_ * H_];
__device__ float g_tmp[H_ * H_];                 // Wq^T @ Wbil
__device__ float g_WfullT[H_ * H_];              // (Wq^T Wbil Wk) transposed
__device__ float g_wvc[H_];                      // Wprj @ Wv
__device__ float g_vp[FLATR];                    // hall . wvc
__device__ float g_po[B_ * M_ * T_];             // per-slot partial output

// ---------------- tf32 helpers ----------------
__device__ __forceinline__ uint32_t f2tf32(float f) {
    uint32_t o;
    asm("cvt.rna.tf32.f32 %0, %1;" : "=r"(o) : "f"(f));
    return o;
}

__device__ __forceinline__ void mma_tf32(float& d0, float& d1, float& d2, float& d3,
                                         uint32_t a0, uint32_t a1, uint32_t a2, uint32_t a3,
                                         uint32_t b0, uint32_t b1) {
    asm volatile(
        "mma.sync.aligned.m16n8k8.row.col.f32.tf32.tf32.f32 "
        "{%0,%1,%2,%3}, {%4,%5,%6,%7}, {%8,%9}, {%0,%1,%2,%3};\n"
        : "+f"(d0), "+f"(d1), "+f"(d2), "+f"(d3)
        : "r"(a0), "r"(a1), "r"(a2), "r"(a3), "r"(b0), "r"(b1));
}

// ---------------- prep kernels ----------------
__global__ void prep_tmp(const float* __restrict__ Wq, const float* __restrict__ Wbil,
                         float* __restrict__ tmp) {
    int k = blockIdx.x, c = threadIdx.x;
    float s = 0.f;
    for (int a = 0; a < H_; a++) s += Wq[a * H_ + k] * Wbil[a * H_ + c];
    tmp[k * H_ + c] = s;
}

__global__ void prep_wfull(const float* __restrict__ tmp, const float* __restrict__ Wk,
                           float* __restrict__ WfullT) {
    int k = blockIdx.x, hp = threadIdx.x;
    float s = 0.f;
    for (int c = 0; c < H_; c++) s += tmp[k * H_ + c] * Wk[c * H_ + hp];
    WfullT[hp * H_ + k] = s;
}

__global__ void prep_wvc(const float* __restrict__ Wprj, const float* __restrict__ Wv,
                         float* __restrict__ wvc) {
    int hp = threadIdx.x;
    float s = 0.f;
    for (int h = 0; h < H_; h++) s += Wprj[h] * Wv[h * H_ + hp];
    wvc[hp] = s;
}

__global__ void init_h(const float* __restrict__ node_hidden,
                       const float* __restrict__ ngh_hidden,
                       float* __restrict__ h) {
    int row = blockIdx.x, u = threadIdx.x;
    float v = (row < B_) ? node_hidden[row * H_ + u]
                         : ngh_hidden[(row - B_) * H_ + u];
    h[row * H_ + u] = v;
}

// ---------------- tf32 tensor-core GEMM: C[M x 768] = X[M x 128] @ W[768 x 128]^T ----
// grid (6, M/128), block 256 (8 warps, 2x4 layout, warp tile 64x32)
__global__ __launch_bounds__(256) void gemm_xw(const float* __restrict__ X,
                                               const float* __restrict__ W,
                                               float* __restrict__ C) {
    __shared__ uint32_t As[128 * 68];
    __shared__ uint32_t Bs[128 * 68];
    int tid = threadIdx.x;
    int warp = tid >> 5, lane = tid & 31;
    int gr = lane >> 2, gc = lane & 3;
    int m0 = blockIdx.y * 128, n0 = blockIdx.x * 128;
    int wm = (warp >> 2) * 64, wn = (warp & 3) * 32;

    float acc[4][4][4] = {};

    for (int k0 = 0; k0 < 128; k0 += 64) {
        // stage A and B (tf32-converted), 68-word row stride
        for (int i = tid; i < 2048; i += 256) {
            int r = i >> 4, c4 = (i & 15) * 4;
            float4 v = *(const float4*)(X + (size_t)(m0 + r) * 128 + k0 + c4);
            uint4 u = { f2tf32(v.x), f2tf32(v.y), f2tf32(v.z), f2tf32(v.w) };
            *(uint4*)(As + r * 68 + c4) = u;
        }
        for (int i = tid; i < 2048; i += 256) {
            int r = i >> 4, c4 = (i & 15) * 4;
            float4 v = *(const float4*)(W + (size_t)(n0 + r) * 128 + k0 + c4);
            uint4 u = { f2tf32(v.x), f2tf32(v.y), f2tf32(v.z), f2tf32(v.w) };
            *(uint4*)(Bs + r * 68 + c4) = u;
        }
        __syncthreads();

        #pragma unroll
        for (int kk = 0; kk < 8; kk++) {
            uint32_t a[4][4], b[4][2];
            #pragma unroll
            for (int mt = 0; mt < 4; mt++) {
                int r = wm + mt * 16 + gr;
                a[mt][0] = As[r * 68 + kk * 8 + gc];
                a[mt][1] = As[(r + 8) * 68 + kk * 8 + gc];
                a[mt][2] = As[r * 68 + kk * 8 + gc + 4];
                a[mt][3] = As[(r + 8) * 68 + kk * 8 + gc + 4];
            }
            #pragma unroll
            for (int nt = 0; nt < 4; nt++) {
                int n = wn + nt * 8 + gr;
                b[nt][0] = Bs[n * 68 + kk * 8 + gc];
                b[nt][1] = Bs[n * 68 + kk * 8 + gc + 4];
            }
            #pragma unroll
            for (int mt = 0; mt < 4; mt++)
                #pragma unroll
                for (int nt = 0; nt < 4; nt++)
                    mma_tf32(acc[mt][nt][0], acc[mt][nt][1], acc[mt][nt][2], acc[mt][nt][3],
                             a[mt][0], a[mt][1], a[mt][2], a[mt][3], b[nt][0], b[nt][1]);
        }
        __syncthreads();
    }

    // epilogue: c0,c1 at (row, 2*gc), c2,c3 at (row+8, 2*gc)
    #pragma unroll
    for (int mt = 0; mt < 4; mt++) {
        int r1 = m0 + wm + mt * 16 + gr;
        #pragma unroll
        for (int nt = 0; nt < 4; nt++) {
            int col = n0 + wn + nt * 8 + 2 * gc;
            float2 v0 = { acc[mt][nt][0], acc[mt][nt][1] };
            float2 v1 = { acc[mt][nt][2], acc[mt][nt][3] };
            *(float2*)(C + (size_t)r1 * 768 + col) = v0;
            *(float2*)(C + (size_t)(r1 + 8) * 768 + col) = v1;
        }
    }
}

// ---------------- GRU recurrent step: tf32 mma GEMM + fused gates ----------------
// grid (8, 17): x = unit tile (32 units x 3 gates = 96 cols), y = 64-row tile
__global__ __launch_bounds__(256) void gru_step_mma(
    const float* __restrict__ hcur, float* __restrict__ hnext,
    const float* __restrict__ gi,
    const float* __restrict__ Whh_node, const float* __restrict__ Whh_ngh,
    const float* __restrict__ bih_node, const float* __restrict__ bhh_node,
    const float* __restrict__ bih_ngh,  const float* __restrict__ bhh_ngh,
    float* __restrict__ hall, float* __restrict__ nodeout, int t)
{
    __shared__ uint32_t Hs[64 * 68];
    __shared__ uint32_t Ws[96 * 68];   // aliased as GH[64][100] after GEMM
    float* GH = (float*)Ws;

    int tid = threadIdx.x;
    int warp = tid >> 5, lane = tid & 31;
    int gr = lane >> 2, gc = lane & 3;
    int j0 = blockIdx.x * 32;
    int m0 = blockIdx.y * 64;
    bool is_node = (blockIdx.y == 0);
    const float* Whh = is_node ? Whh_node : Whh_ngh;

    int wm = (warp >> 2) * 32;         // 0 or 32
    int wn = (warp & 3) * 24;          // 0,24,48,72

    float acc[2][3][4] = {};

    for (int k0 = 0; k0 < 256; k0 += 64) {
        for (int i = tid; i < 1024; i += 256) {
            int r = i >> 4, c4 = (i & 15) * 4;
            float4 v = *(const float4*)(hcur + (size_t)(m0 + r) * 256 + k0 + c4);
            uint4 u = { f2tf32(v.x), f2tf32(v.y), f2tf32(v.z), f2tf32(v.w) };
            *(uint4*)(Hs + r * 68 + c4) = u;
        }
        for (int i = tid; i < 1536; i += 256) {
            int r = i >> 4, c4 = (i & 15) * 4;
            int g = r >> 5, uu = r & 31;
            float4 v = *(const float4*)(Whh + (size_t)(g * 256 + j0 + uu) * 256 + k0 + c4);
            uint4 u = { f2tf32(v.x), f2tf32(v.y), f2tf32(v.z), f2tf32(v.w) };
            *(uint4*)(Ws + r * 68 + c4) = u;
        }
        __syncthreads();

        #pragma unroll
        for (int kk = 0; kk < 8; kk++) {
            uint32_t a[2][4], b[3][2];
            #pragma unroll
            for (int mt = 0; mt < 2; mt++) {
                int r = wm + mt * 16 + gr;
                a[mt][0] = Hs[r * 68 + kk * 8 + gc];
                a[mt][1] = Hs[(r + 8) * 68 + kk * 8 + gc];
                a[mt][2] = Hs[r * 68 + kk * 8 + gc + 4];
                a[mt][3] = Hs[(r + 8) * 68 + kk * 8 + gc + 4];
            }
            #pragma unroll
            for (int nt = 0; nt < 3; nt++) {
                int n = wn + nt * 8 + gr;
                b[nt][0] = Ws[n * 68 + kk * 8 + gc];
                b[nt][1] = Ws[n * 68 + kk * 8 + gc + 4];
            }
            #pragma unroll
            for (int mt = 0; mt < 2; mt++)
                #pragma unroll
                for (int nt = 0; nt < 3; nt++)
                    mma_tf32(acc[mt][nt][0], acc[mt][nt][1], acc[mt][nt][2], acc[mt][nt][3],
                             a[mt][0], a[mt][1], a[mt][2], a[mt][3], b[nt][0], b[nt][1]);
        }
        __syncthreads();
    }

    // stage gh through smem (alias over Ws), stride 100 for conflict-free reads
    #pragma unroll
    for (int mt = 0; mt < 2; mt++) {
        int r1 = wm + mt * 16 + gr;
        #pragma unroll
        for (int nt = 0; nt < 3; nt++) {
            int col = wn + nt * 8 + 2 * gc;
            GH[r1 * 100 + col]       = acc[mt][nt][0];
            GH[r1 * 100 + col + 1]   = acc[mt][nt][1];
            GH[(r1 + 8) * 100 + col]     = acc[mt][nt][2];
            GH[(r1 + 8) * 100 + col + 1] = acc[mt][nt][3];
        }
    }
    __syncthreads();

    // gate math: thread (warp, lane) -> unit j = j0+lane, rows warp*8..+7
    const float* bih = is_node ? bih_node : bih_ngh;
    const float* bhh = is_node ? bhh_node : bhh_ngh;
    int j = j0 + lane;
    float bir = bih[j], biz = bih[256 + j], bin = bih[512 + j];
    float bhr = bhh[j], bhz = bhh[256 + j], bhn = bhh[512 + j];

    #pragma unroll
    for (int rr = 0; rr < 8; rr++) {
        int row = warp * 8 + rr;
        int R = m0 + row;
        size_t gbase = ((size_t)R * T_ + t) * 768;
        float gir = gi[gbase + j]       + bir;
        float giz = gi[gbase + 256 + j] + biz;
        float gin = gi[gbase + 512 + j] + bin;
        float ghr = GH[row * 100 + lane]      + bhr;
        float ghz = GH[row * 100 + 32 + lane] + bhz;
        float ghn = GH[row * 100 + 64 + lane] + bhn;
        float r = 1.f / (1.f + expf(-(gir + ghr)));
        float z = 1.f / (1.f + expf(-(giz + ghz)));
        float n = tanhf(gin + r * ghn);
        float hp = hcur[(size_t)R * H_ + j];
        float hnew = (1.f - z) * n + z * hp;
        hnext[(size_t)R * H_ + j] = hnew;
        int b, m;
        if (R < B_) { b = R; m = 0; }
        else { int q = R - B_; b = q >> 4; m = (q & 15) + 1; }
        hall[(((size_t)b * M_ + m) * T_ + t) * H_ + j] = hnew;
        if (R < B_) nodeout[((size_t)R * T_ + t) * H_ + j] = hnew;
    }
}

// ---------------- generic fp32 GEMM (kept for small Q2): C = A @ B^T ----------------
__global__ __launch_bounds__(256) void sgemm128(const float* __restrict__ A,
                                                const float* __restrict__ B,
                                                float* __restrict__ C,
                                                int M, int N, int K) {
    __shared__ float As[8][128];
    __shared__ float Bs[8][128];
    int tid = threadIdx.x;
    int tx = tid & 15, ty = tid >> 4;
    int m0 = blockIdx.y * 128, n0 = blockIdx.x * 128;
    float acc[8][8] = {};
    for (int k0 = 0; k0 < K; k0 += 8) {
        #pragma unroll
        for (int i = 0; i < 4; i++) {
            int idx = tid + i * 256;
            int r = idx >> 3, c = idx & 7;
            As[c][r] = A[(size_t)(m0 + r) * K + k0 + c];
            Bs[c][r] = B[(size_t)(n0 + r) * K + k0 + c];
        }
        __syncthreads();
        #pragma unroll
        for (int k = 0; k < 8; k++) {
            float a[8], bv[8];
            #pragma unroll
            for (int i = 0; i < 8; i++) a[i] = As[k][ty * 8 + i];
            #pragma unroll
            for (int j = 0; j < 8; j++) bv[j] = Bs[k][tx * 8 + j];
            #pragma unroll
            for (int i = 0; i < 8; i++)
                #pragma unroll
                for (int j = 0; j < 8; j++) acc[i][j] += a[i] * bv[j];
        }
        __syncthreads();
    }
    #pragma unroll
    for (int i = 0; i < 8; i++)
        #pragma unroll
        for (int j = 0; j < 8; j++)
            C[(size_t)(m0 + ty * 8 + i) * N + n0 + tx * 8 + j] = acc[i][j];
}

// ---------------- vproj: hall . wvc (warp per row) ----------------
__global__ void vproj_kernel(const float* __restrict__ hall, const float* __restrict__ wvc,
                             float* __restrict__ vp) {
    int warp = threadIdx.x >> 5, lane = threadIdx.x & 31;
    int row = blockIdx.x * 8 + warp;
    const float* hrow = hall + (size_t)row * H_;
    float s = 0.f;
    #pragma unroll
    for (int i = 0; i < 8; i++) s += hrow[lane + i * 32] * wvc[lane + i * 32];
    #pragma unroll
    for (int o = 16; o; o >>= 1) s += __shfl_xor_sync(0xffffffffu, s, o);
    if (lane == 0) vp[row] = s;
}

// ---------------- fused attention: S -> mask -> softmax -> A out + A@vproj ----------------
__global__ __launch_bounds__(256) void attn_kernel(
    const float* __restrict__ Q2, const float* __restrict__ hall,
    const float* __restrict__ vp, const float* __restrict__ bbil,
    float* __restrict__ A_out, float* __restrict__ po)
{
    __shared__ float Qs[16][64];
    __shared__ float Ks[16][64];
    __shared__ float Ssm[64 * 65];
    __shared__ float vps[64];
    __shared__ float bb[64];

    int bm = blockIdx.x;
    int b = bm / M_;
    int tid = threadIdx.x;
    const float* qsrc = Q2 + (size_t)b * T_ * H_;
    const float* ksrc = hall + (size_t)bm * T_ * H_;
    if (tid < 64) { vps[tid] = vp[bm * 64 + tid]; bb[tid] = bbil[tid]; }

    int tx = tid & 15, ty = tid >> 4;
    float acc[4][4] = {};
    for (int k0 = 0; k0 < H_; k0 += 16) {
        #pragma unroll
        for (int i = 0; i < 4; i++) {
            int idx = tid + i * 256;
            int r = idx >> 4, c = idx & 15;
            Qs[c][r] = qsrc[r * H_ + k0 + c];
            Ks[c][r] = ksrc[r * H_ + k0 + c];
        }
        __syncthreads();
        #pragma unroll
        for (int k = 0; k < 16; k++) {
            float q[4], kv[4];
            #pragma unroll
            for (int i = 0; i < 4; i++) q[i]  = Qs[k][ty + 16 * i];
            #pragma unroll
            for (int j = 0; j < 4; j++) kv[j] = Ks[k][tx + 16 * j];
            #pragma unroll
            for (int i = 0; i < 4; i++)
                #pragma unroll
                for (int j = 0; j < 4; j++) acc[i][j] += q[i] * kv[j];
        }
        __syncthreads();
    }
    #pragma unroll
    for (int i = 0; i < 4; i++)
        #pragma unroll
        for (int j = 0; j < 4; j++)
            Ssm[(ty + 16 * i) * 65 + tx + 16 * j] = acc[i][j];
    __syncthreads();

    int warp = tid >> 5, lane = tid & 31;
    for (int rr = 0; rr < 8; rr++) {
        int t = warp * 8 + rr;
        int s2 = lane + 32;
        bool v1ok = (lane <= t), v2ok = (s2 <= t);
        float v1 = v1ok ? Ssm[t * 65 + lane] + bb[lane] : -3.0e38f;
        float v2 = v2ok ? Ssm[t * 65 + s2]   + bb[s2]   : -3.0e38f;
        float mx = fmaxf(v1, v2);
        #pragma unroll
        for (int o = 16; o; o >>= 1) mx = fmaxf(mx, __shfl_xor_sync(0xffffffffu, mx, o));
        float p1 = v1ok ? expf(v1 - mx) : 0.f;
        float p2 = v2ok ? expf(v2 - mx) : 0.f;
        float sum = p1 + p2;
        #pragma unroll
        for (int o = 16; o; o >>= 1) sum += __shfl_xor_sync(0xffffffffu, sum, o);
        float inv = 1.f / sum;
        float a1 = p1 * inv, a2 = p2 * inv;
        size_t abase = ((size_t)bm * 64 + t) * 64;
        A_out[abase + lane]      = a1;
        A_out[abase + lane + 32] = a2;
        float pv = a1 * vps[lane] + a2 * vps[s2];
        #pragma unroll
        for (int o = 16; o; o >>= 1) pv += __shfl_xor_sync(0xffffffffu, pv, o);
        if (lane == 0) po[bm * 64 + t] = pv;
    }
}

// ---------------- finalize: out reduce over slots + hT copies ----------------
__global__ void finalize(const float* __restrict__ po, const float* __restrict__ bprj,
                         const float* __restrict__ hfin, float* __restrict__ out) {
    int idx = blockIdx.x * 256 + threadIdx.x;
    if (idx < 4096) {
        int b = idx >> 6, t = idx & 63;
        float s = 17.f * bprj[0];
        #pragma unroll
        for (int m = 0; m < M_; m++) s += po[(b * M_ + m) * 64 + t];
        out[idx] = s;
    } else if (idx < OFF_GHT) {
        out[idx] = hfin[idx - OFF_NHT];               // node_hT
    } else if (idx < OFF_A) {
        out[idx] = hfin[B_ * H_ + (idx - OFF_GHT)];   // ngh_hT
    }
}

// ---------------- launch ----------------
extern "C" void kernel_launch(void* const* d_in, const int* in_sizes, int n_in,
                              void* d_out, int out_size) {
    const float* node_input   = (const float*)d_in[0];
    const float* node_hidden  = (const float*)d_in[1];
    const float* ngh_input    = (const float*)d_in[2];
    const float* ngh_hidden   = (const float*)d_in[3];
    // d_in[4] = s_len (unused by reference)
    const float* Wih_node = (const float*)d_in[5];
    const float* Whh_node = (const float*)d_in[6];
    const float* bih_node = (const float*)d_in[7];
    const float* bhh_node = (const float*)d_in[8];
    const float* Wih_ngh  = (const float*)d_in[9];
    const float* Whh_ngh  = (const float*)d_in[10];
    const float* bih_ngh  = (const float*)d_in[11];
    const float* bhh_ngh  = (const float*)d_in[12];
    const float* Wq   = (const float*)d_in[13];
    const float* Wk   = (const float*)d_in[14];
    const float* Wv   = (const float*)d_in[15];
    const float* Wbil = (const float*)d_in[16];
    const float* bbil = (const float*)d_in[17];
    const float* Wprj = (const float*)d_in[18];
    const float* bprj = (const float*)d_in[19];
    float* out = (float*)d_out;

    float *gi, *h0, *h1, *hall, *nodeout, *Q2, *tmp, *WfullT, *wvc, *vpd, *pod;
    cudaGetSymbolAddress((void**)&gi, g_gi);
    cudaGetSymbolAddress((void**)&h0, g_h0);
    cudaGetSymbolAddress((void**)&h1, g_h1);
    cudaGetSymbolAddress((void**)&hall, g_hall);
    cudaGetSymbolAddress((void**)&nodeout, g_nodeout);
    cudaGetSymbolAddress((void**)&Q2, g_Q2);
    cudaGetSymbolAddress((void**)&tmp, g_tmp);
    cudaGetSymbolAddress((void**)&WfullT, g_WfullT);
    cudaGetSymbolAddress((void**)&wvc, g_wvc);
    cudaGetSymbolAddress((void**)&vpd, g_vp);
    cudaGetSymbolAddress((void**)&pod, g_po);

    // weight prep (tiny)
    prep_tmp<<<256, 256>>>(Wq, Wbil, tmp);
    prep_wfull<<<256, 256>>>(tmp, Wk, WfullT);
    prep_wvc<<<1, 256>>>(Wprj, Wv, wvc);
    init_h<<<RALL, 256>>>(node_hidden, ngh_hidden, h0);

    // hoisted input-side GRU GEMMs via tensor cores: gi = X @ Wih^T
    gemm_xw<<<dim3(6, 32), 256>>>(node_input, Wih_node, gi);
    gemm_xw<<<dim3(6, 512), 256>>>(ngh_input, Wih_ngh, gi + (size_t)4096 * 768);

    // sequential recurrence (tensor-core step GEMM + fused gates)
    for (int t = 0; t < T_; t++) {
        const float* hc = (t & 1) ? h1 : h0;
        float* hn = (t & 1) ? h0 : h1;
        gru_step_mma<<<dim3(8, 17), 256>>>(hc, hn, gi, Whh_node, Whh_ngh,
                                           bih_node, bhh_node, bih_ngh, bhh_ngh,
                                           hall, nodeout, t);
    }

    // attention
    sgemm128<<<dim3(2, 32), 256>>>(nodeout, WfullT, Q2, 4096, 256, 256);
    vproj_kernel<<<FLATR / 8, 256>>>(hall, wvc, vpd);
    attn_kernel<<<B_ * M_, 256>>>(Q2, hall, vpd, bbil, out + OFF_A, pod);

    finalize<<<(OFF_A + 255) / 256, 256>>>(pod, bprj, h0 /*T even -> final in h0*/, out);
}

// round 3
// speedup vs baseline: 3.6638x; 1.4368x over previous
#include <cuda_runtime.h>
#include <cuda_bf16.h>
#include <math.h>
#include <stdint.h>

// Problem dims
#define B_  64
#define N_  16
#define T_  64
#define D_  128
#define H_  256
#define M_  17          // N+1 slots
#define RALL 1088       // B + B*N batch rows
#define FLATR 69632     // RALL*T  (also B*M_*T_)
#define NBLK 136        // persistent GRU grid (8 j-tiles x 17 m-tiles)

// Output offsets (concat of: out(4096), node_hT(16384), ngh_hT(262144), A(4456448))
#define OFF_OUT 0
#define OFF_NHT 4096
#define OFF_GHT 20480
#define OFF_A   282624

// ---------------- device scratch (no runtime allocation allowed) ----------------
__device__ float g_gi[(size_t)FLATR * 768];      // precomputed x@Wih.T, [(r*T+t)*768+j]
__device__ float g_h0[RALL * H_];                // ping-pong hidden state
__device__ float g_h1[RALL * H_];
__device__ float g_hall[(size_t)FLATR * H_];     // kv layout [((b*17+m)*64+t)*256+h]
__device__ float g_nodeout[(size_t)B_ * T_ * H_];// [(b*64+t)*256+h]
__device__ float g_Q2[(size_t)B_ * T_ * H_];
__device__ float g_tmp[H_ * H_];                 // Wq^T @ Wbil
__device__ float g_WfullT[H_ * H_];              // (Wq^T Wbil Wk) transposed
__device__ float g_wvc[H_];                      // Wprj @ Wv
__device__ float g_vp[FLATR];                    // hall . wvc
__device__ float g_po[B_ * M_ * T_];             // per-slot partial output
__device__ unsigned g_bar;                       // grid barrier counter

// ---------------- tf32 helpers ----------------
__device__ __forceinline__ uint32_t f2tf32(float f) {
    uint32_t o;
    asm("cvt.rna.tf32.f32 %0, %1;" : "=r"(o) : "f"(f));
    return o;
}

__device__ __forceinline__ void mma_tf32(float& d0, float& d1, float& d2, float& d3,
                                         uint32_t a0, uint32_t a1, uint32_t a2, uint32_t a3,
                                         uint32_t b0, uint32_t b1) {
    asm volatile(
        "mma.sync.aligned.m16n8k8.row.col.f32.tf32.tf32.f32 "
        "{%0,%1,%2,%3}, {%4,%5,%6,%7}, {%8,%9}, {%0,%1,%2,%3};\n"
        : "+f"(d0), "+f"(d1), "+f"(d2), "+f"(d3)
        : "r"(a0), "r"(a1), "r"(a2), "r"(a3), "r"(b0), "r"(b1));
}

// ---------------- prep kernels ----------------
__global__ void prep_tmp(const float* __restrict__ Wq, const float* __restrict__ Wbil,
                         float* __restrict__ tmp) {
    int k = blockIdx.x, c = threadIdx.x;
    float s = 0.f;
    for (int a = 0; a < H_; a++) s += Wq[a * H_ + k] * Wbil[a * H_ + c];
    tmp[k * H_ + c] = s;
}

__global__ void prep_wfull(const float* __restrict__ tmp, const float* __restrict__ Wk,
                           float* __restrict__ WfullT) {
    int k = blockIdx.x, hp = threadIdx.x;
    float s = 0.f;
    for (int c = 0; c < H_; c++) s += tmp[k * H_ + c] * Wk[c * H_ + hp];
    WfullT[hp * H_ + k] = s;
}

__global__ void prep_wvc(const float* __restrict__ Wprj, const float* __restrict__ Wv,
                         float* __restrict__ wvc) {
    int hp = threadIdx.x;
    float s = 0.f;
    for (int h = 0; h < H_; h++) s += Wprj[h] * Wv[h * H_ + hp];
    wvc[hp] = s;
    if (hp == 0) g_bar = 0;     // reset grid barrier every launch/replay
}

__global__ void init_h(const float* __restrict__ node_hidden,
                       const float* __restrict__ ngh_hidden,
                       float* __restrict__ h) {
    int row = blockIdx.x, u = threadIdx.x;
    float v = (row < B_) ? node_hidden[row * H_ + u]
                         : ngh_hidden[(row - B_) * H_ + u];
    h[row * H_ + u] = v;
}

// ---------------- tf32 tensor-core GEMM: C[M x 768] = X[M x 128] @ W[768 x 128]^T ----
// grid (6, M/128), block 256 (8 warps, 2x4 layout, warp tile 64x32)
__global__ __launch_bounds__(256) void gemm_xw(const float* __restrict__ X,
                                               const float* __restrict__ W,
                                               float* __restrict__ C) {
    __shared__ uint32_t As[128 * 68];
    __shared__ uint32_t Bs[128 * 68];
    int tid = threadIdx.x;
    int warp = tid >> 5, lane = tid & 31;
    int gr = lane >> 2, gc = lane & 3;
    int m0 = blockIdx.y * 128, n0 = blockIdx.x * 128;
    int wm = (warp >> 2) * 64, wn = (warp & 3) * 32;

    float acc[4][4][4] = {};

    for (int k0 = 0; k0 < 128; k0 += 64) {
        for (int i = tid; i < 2048; i += 256) {
            int r = i >> 4, c4 = (i & 15) * 4;
            float4 v = *(const float4*)(X + (size_t)(m0 + r) * 128 + k0 + c4);
            uint4 u = { f2tf32(v.x), f2tf32(v.y), f2tf32(v.z), f2tf32(v.w) };
            *(uint4*)(As + r * 68 + c4) = u;
        }
        for (int i = tid; i < 2048; i += 256) {
            int r = i >> 4, c4 = (i & 15) * 4;
            float4 v = *(const float4*)(W + (size_t)(n0 + r) * 128 + k0 + c4);
            uint4 u = { f2tf32(v.x), f2tf32(v.y), f2tf32(v.z), f2tf32(v.w) };
            *(uint4*)(Bs + r * 68 + c4) = u;
        }
        __syncthreads();

        #pragma unroll
        for (int kk = 0; kk < 8; kk++) {
            uint32_t a[4][4], b[4][2];
            #pragma unroll
            for (int mt = 0; mt < 4; mt++) {
                int r = wm + mt * 16 + gr;
                a[mt][0] = As[r * 68 + kk * 8 + gc];
                a[mt][1] = As[(r + 8) * 68 + kk * 8 + gc];
                a[mt][2] = As[r * 68 + kk * 8 + gc + 4];
                a[mt][3] = As[(r + 8) * 68 + kk * 8 + gc + 4];
            }
            #pragma unroll
            for (int nt = 0; nt < 4; nt++) {
                int n = wn + nt * 8 + gr;
                b[nt][0] = Bs[n * 68 + kk * 8 + gc];
                b[nt][1] = Bs[n * 68 + kk * 8 + gc + 4];
            }
            #pragma unroll
            for (int mt = 0; mt < 4; mt++)
                #pragma unroll
                for (int nt = 0; nt < 4; nt++)
                    mma_tf32(acc[mt][nt][0], acc[mt][nt][1], acc[mt][nt][2], acc[mt][nt][3],
                             a[mt][0], a[mt][1], a[mt][2], a[mt][3], b[nt][0], b[nt][1]);
        }
        __syncthreads();
    }

    #pragma unroll
    for (int mt = 0; mt < 4; mt++) {
        int r1 = m0 + wm + mt * 16 + gr;
        #pragma unroll
        for (int nt = 0; nt < 4; nt++) {
            int col = n0 + wn + nt * 8 + 2 * gc;
            float2 v0 = { acc[mt][nt][0], acc[mt][nt][1] };
            float2 v1 = { acc[mt][nt][2], acc[mt][nt][3] };
            *(float2*)(C + (size_t)r1 * 768 + col) = v0;
            *(float2*)(C + (size_t)(r1 + 8) * 768 + col) = v1;
        }
    }
}

// ---------------- persistent GRU: all 64 steps in one kernel ----------------
// grid NBLK=136 blocks: jt = bx&7 (32-unit tile), mt = bx>>3 (64-row tile)
// Whh slice loaded ONCE into smem (tf32). Per step: grid barrier -> stage h ->
// mma -> gates -> store. h reads bypass L1 (__ldcg) because buffers are
// re-read after cross-block writes within the same kernel.
__global__ __launch_bounds__(256, 1) void gru_persist(
    const float* __restrict__ gi,
    const float* __restrict__ Whh_node, const float* __restrict__ Whh_ngh,
    const float* __restrict__ bih_node, const float* __restrict__ bhh_node,
    const float* __restrict__ bih_ngh,  const float* __restrict__ bhh_ngh,
    float* __restrict__ h0, float* __restrict__ h1,
    float* __restrict__ hall, float* __restrict__ nodeout)
{
    extern __shared__ uint32_t sh[];
    uint32_t* Ws = sh;                 // 96 x 260
    uint32_t* Hs = sh + 96 * 260;      // 64 x 260 (aliased as GH[64][100] post-mma)
    float* GH = (float*)Hs;

    int tid = threadIdx.x;
    int warp = tid >> 5, lane = tid & 31;
    int gr = lane >> 2, gc = lane & 3;
    int bx = blockIdx.x;
    int jt = bx & 7, mt = bx >> 3;
    int j0 = jt * 32, m0 = mt * 64;
    bool is_node = (mt == 0);
    const float* Whh = is_node ? Whh_node : Whh_ngh;
    int wm = (warp >> 2) * 32;         // 0 or 32
    int wn = (warp & 3) * 24;          // 0,24,48,72

    // ---- load weight slice once: rows = 3 gates x 32 units, K=256 ----
    for (int i = tid; i < 96 * 64; i += 256) {
        int r = i >> 6, c4 = (i & 63) * 4;
        int g = r >> 5, uu = r & 31;
        float4 v = *(const float4*)(Whh + (size_t)(g * 256 + j0 + uu) * 256 + c4);
        uint4 u = { f2tf32(v.x), f2tf32(v.y), f2tf32(v.z), f2tf32(v.w) };
        *(uint4*)(Ws + r * 260 + c4) = u;
    }

    // biases (thread -> unit j = j0+lane)
    const float* bih = is_node ? bih_node : bih_ngh;
    const float* bhh = is_node ? bhh_node : bhh_ngh;
    int j = j0 + lane;
    float bir = bih[j], biz = bih[256 + j], bin = bih[512 + j];
    float bhr = bhh[j], bhz = bhh[256 + j], bhn = bhh[512 + j];
    __syncthreads();

    for (int t = 0; t < T_; t++) {
        const float* hcur = (t & 1) ? h1 : h0;
        float* hnext = (t & 1) ? h0 : h1;

        // ---- stage h tile (L1-bypassed) ----
        for (int i = tid; i < 64 * 64; i += 256) {
            int r = i >> 6, c4 = (i & 63) * 4;
            float4 v = __ldcg((const float4*)(hcur + (size_t)(m0 + r) * 256 + c4));
            uint4 u = { f2tf32(v.x), f2tf32(v.y), f2tf32(v.z), f2tf32(v.w) };
            *(uint4*)(Hs + r * 260 + c4) = u;
        }
        __syncthreads();

        // ---- gh = h @ Whh_slice^T via tf32 mma ----
        float acc[2][3][4] = {};
        #pragma unroll
        for (int kk = 0; kk < 32; kk++) {
            uint32_t a[2][4], b[3][2];
            #pragma unroll
            for (int mm = 0; mm < 2; mm++) {
                int r = wm + mm * 16 + gr;
                a[mm][0] = Hs[r * 260 + kk * 8 + gc];
                a[mm][1] = Hs[(r + 8) * 260 + kk * 8 + gc];
                a[mm][2] = Hs[r * 260 + kk * 8 + gc + 4];
                a[mm][3] = Hs[(r + 8) * 260 + kk * 8 + gc + 4];
            }
            #pragma unroll
            for (int nt = 0; nt < 3; nt++) {
                int n = wn + nt * 8 + gr;
                b[nt][0] = Ws[n * 260 + kk * 8 + gc];
                b[nt][1] = Ws[n * 260 + kk * 8 + gc + 4];
            }
            #pragma unroll
            for (int mm = 0; mm < 2; mm++)
                #pragma unroll
                for (int nt = 0; nt < 3; nt++)
                    mma_tf32(acc[mm][nt][0], acc[mm][nt][1], acc[mm][nt][2], acc[mm][nt][3],
                             a[mm][0], a[mm][1], a[mm][2], a[mm][3], b[nt][0], b[nt][1]);
        }
        __syncthreads();   // Hs consumed; safe to alias as GH

        #pragma unroll
        for (int mm = 0; mm < 2; mm++) {
            int r1 = wm + mm * 16 + gr;
            #pragma unroll
            for (int nt = 0; nt < 3; nt++) {
                int col = wn + nt * 8 + 2 * gc;
                GH[r1 * 100 + col]           = acc[mm][nt][0];
                GH[r1 * 100 + col + 1]       = acc[mm][nt][1];
                GH[(r1 + 8) * 100 + col]     = acc[mm][nt][2];
                GH[(r1 + 8) * 100 + col + 1] = acc[mm][nt][3];
            }
        }
        __syncthreads();

        // ---- gates: thread (warp, lane) -> unit j, rows warp*8..+7 ----
        #pragma unroll
        for (int rr = 0; rr < 8; rr++) {
            int row = warp * 8 + rr;
            int R = m0 + row;
            size_t gbase = ((size_t)R * T_ + t) * 768;
            float gir = gi[gbase + j]       + bir;
            float giz = gi[gbase + 256 + j] + biz;
            float gin = gi[gbase + 512 + j] + bin;
            float ghr = GH[row * 100 + lane]      + bhr;
            float ghz = GH[row * 100 + 32 + lane] + bhz;
            float ghn = GH[row * 100 + 64 + lane] + bhn;
            float r = 1.f / (1.f + expf(-(gir + ghr)));
            float z = 1.f / (1.f + expf(-(giz + ghz)));
            float n = tanhf(gin + r * ghn);
            float hp = __ldcg(hcur + (size_t)R * H_ + j);
            float hnew = (1.f - z) * n + z * hp;
            hnext[(size_t)R * H_ + j] = hnew;
            int b, m;
            if (R < B_) { b = R; m = 0; }
            else { int q = R - B_; b = q >> 4; m = (q & 15) + 1; }
            hall[(((size_t)b * M_ + m) * T_ + t) * H_ + j] = hnew;
            if (R < B_) nodeout[((size_t)R * T_ + t) * H_ + j] = hnew;
        }

        // ---- grid barrier (all 136 blocks co-resident: 1 block/SM) ----
        __syncthreads();
        if (tid == 0) {
            __threadfence();
            atomicAdd(&g_bar, 1u);
            unsigned target = (unsigned)NBLK * (t + 1);
            while (*(volatile unsigned*)&g_bar < target) { }
            __threadfence();
        }
        __syncthreads();
    }
}

// ---------------- generic fp32 GEMM (Q2): C = A @ B^T ----------------
__global__ __launch_bounds__(256) void sgemm128(const float* __restrict__ A,
                                                const float* __restrict__ B,
                                                float* __restrict__ C,
                                                int M, int N, int K) {
    __shared__ float As[8][128];
    __shared__ float Bs[8][128];
    int tid = threadIdx.x;
    int tx = tid & 15, ty = tid >> 4;
    int m0 = blockIdx.y * 128, n0 = blockIdx.x * 128;
    float acc[8][8] = {};
    for (int k0 = 0; k0 < K; k0 += 8) {
        #pragma unroll
        for (int i = 0; i < 4; i++) {
            int idx = tid + i * 256;
            int r = idx >> 3, c = idx & 7;
            As[c][r] = A[(size_t)(m0 + r) * K + k0 + c];
            Bs[c][r] = B[(size_t)(n0 + r) * K + k0 + c];
        }
        __syncthreads();
        #pragma unroll
        for (int k = 0; k < 8; k++) {
            float a[8], bv[8];
            #pragma unroll
            for (int i = 0; i < 8; i++) a[i] = As[k][ty * 8 + i];
            #pragma unroll
            for (int jj = 0; jj < 8; jj++) bv[jj] = Bs[k][tx * 8 + jj];
            #pragma unroll
            for (int i = 0; i < 8; i++)
                #pragma unroll
                for (int jj = 0; jj < 8; jj++) acc[i][jj] += a[i] * bv[jj];
        }
        __syncthreads();
    }
    #pragma unroll
    for (int i = 0; i < 8; i++)
        #pragma unroll
        for (int jj = 0; jj < 8; jj++)
            C[(size_t)(m0 + ty * 8 + i) * N + n0 + tx * 8 + jj] = acc[i][jj];
}

// ---------------- vproj: hall . wvc (warp per row) ----------------
__global__ void vproj_kernel(const float* __restrict__ hall, const float* __restrict__ wvc,
                             float* __restrict__ vp) {
    int warp = threadIdx.x >> 5, lane = threadIdx.x & 31;
    int row = blockIdx.x * 8 + warp;
    const float* hrow = hall + (size_t)row * H_;
    float s = 0.f;
    #pragma unroll
    for (int i = 0; i < 8; i++) s += hrow[lane + i * 32] * wvc[lane + i * 32];
    #pragma unroll
    for (int o = 16; o; o >>= 1) s += __shfl_xor_sync(0xffffffffu, s, o);
    if (lane == 0) vp[row] = s;
}

// ---------------- fused attention: S -> mask -> softmax -> A out + A@vproj ----------------
__global__ __launch_bounds__(256) void attn_kernel(
    const float* __restrict__ Q2, const float* __restrict__ hall,
    const float* __restrict__ vp, const float* __restrict__ bbil,
    float* __restrict__ A_out, float* __restrict__ po)
{
    __shared__ float Qs[16][64];
    __shared__ float Ks[16][64];
    __shared__ float Ssm[64 * 65];
    __shared__ float vps[64];
    __shared__ float bb[64];

    int bm = blockIdx.x;
    int b = bm / M_;
    int tid = threadIdx.x;
    const float* qsrc = Q2 + (size_t)b * T_ * H_;
    const float* ksrc = hall + (size_t)bm * T_ * H_;
    if (tid < 64) { vps[tid] = vp[bm * 64 + tid]; bb[tid] = bbil[tid]; }

    int tx = tid & 15, ty = tid >> 4;
    float acc[4][4] = {};
    for (int k0 = 0; k0 < H_; k0 += 16) {
        #pragma unroll
        for (int i = 0; i < 4; i++) {
            int idx = tid + i * 256;
            int r = idx >> 4, c = idx & 15;
            Qs[c][r] = qsrc[r * H_ + k0 + c];
            Ks[c][r] = ksrc[r * H_ + k0 + c];
        }
        __syncthreads();
        #pragma unroll
        for (int k = 0; k < 16; k++) {
            float q[4], kv[4];
            #pragma unroll
            for (int i = 0; i < 4; i++) q[i]  = Qs[k][ty + 16 * i];
            #pragma unroll
            for (int jj = 0; jj < 4; jj++) kv[jj] = Ks[k][tx + 16 * jj];
            #pragma unroll
            for (int i = 0; i < 4; i++)
                #pragma unroll
                for (int jj = 0; jj < 4; jj++) acc[i][jj] += q[i] * kv[jj];
        }
        __syncthreads();
    }
    #pragma unroll
    for (int i = 0; i < 4; i++)
        #pragma unroll
        for (int jj = 0; jj < 4; jj++)
            Ssm[(ty + 16 * i) * 65 + tx + 16 * jj] = acc[i][jj];
    __syncthreads();

    int warp = tid >> 5, lane = tid & 31;
    for (int rr = 0; rr < 8; rr++) {
        int t = warp * 8 + rr;
        int s2 = lane + 32;
        bool v1ok = (lane <= t), v2ok = (s2 <= t);
        float v1 = v1ok ? Ssm[t * 65 + lane] + bb[lane] : -3.0e38f;
        float v2 = v2ok ? Ssm[t * 65 + s2]   + bb[s2]   : -3.0e38f;
        float mx = fmaxf(v1, v2);
        #pragma unroll
        for (int o = 16; o; o >>= 1) mx = fmaxf(mx, __shfl_xor_sync(0xffffffffu, mx, o));
        float p1 = v1ok ? expf(v1 - mx) : 0.f;
        float p2 = v2ok ? expf(v2 - mx) : 0.f;
        float sum = p1 + p2;
        #pragma unroll
        for (int o = 16; o; o >>= 1) sum += __shfl_xor_sync(0xffffffffu, sum, o);
        float inv = 1.f / sum;
        float a1 = p1 * inv, a2 = p2 * inv;
        size_t abase = ((size_t)bm * 64 + t) * 64;
        A_out[abase + lane]      = a1;
        A_out[abase + lane + 32] = a2;
        float pv = a1 * vps[lane] + a2 * vps[s2];
        #pragma unroll
        for (int o = 16; o; o >>= 1) pv += __shfl_xor_sync(0xffffffffu, pv, o);
        if (lane == 0) po[bm * 64 + t] = pv;
    }
}

// ---------------- finalize: out reduce over slots + hT copies ----------------
__global__ void finalize(const float* __restrict__ po, const float* __restrict__ bprj,
                         const float* __restrict__ hfin, float* __restrict__ out) {
    int idx = blockIdx.x * 256 + threadIdx.x;
    if (idx < 4096) {
        int b = idx >> 6, t = idx & 63;
        float s = 17.f * bprj[0];
        #pragma unroll
        for (int m = 0; m < M_; m++) s += po[(b * M_ + m) * 64 + t];
        out[idx] = s;
    } else if (idx < OFF_GHT) {
        out[idx] = hfin[idx - OFF_NHT];               // node_hT
    } else if (idx < OFF_A) {
        out[idx] = hfin[B_ * H_ + (idx - OFF_GHT)];   // ngh_hT
    }
}

// ---------------- launch ----------------
extern "C" void kernel_launch(void* const* d_in, const int* in_sizes, int n_in,
                              void* d_out, int out_size) {
    const float* node_input   = (const float*)d_in[0];
    const float* node_hidden  = (const float*)d_in[1];
    const float* ngh_input    = (const float*)d_in[2];
    const float* ngh_hidden   = (const float*)d_in[3];
    // d_in[4] = s_len (unused by reference)
    const float* Wih_node = (const float*)d_in[5];
    const float* Whh_node = (const float*)d_in[6];
    const float* bih_node = (const float*)d_in[7];
    const float* bhh_node = (const float*)d_in[8];
    const float* Wih_ngh  = (const float*)d_in[9];
    const float* Whh_ngh  = (const float*)d_in[10];
    const float* bih_ngh  = (const float*)d_in[11];
    const float* bhh_ngh  = (const float*)d_in[12];
    const float* Wq   = (const float*)d_in[13];
    const float* Wk   = (const float*)d_in[14];
    const float* Wv   = (const float*)d_in[15];
    const float* Wbil = (const float*)d_in[16];
    const float* bbil = (const float*)d_in[17];
    const float* Wprj = (const float*)d_in[18];
    const float* bprj = (const float*)d_in[19];
    float* out = (float*)d_out;

    float *gi, *h0, *h1, *hall, *nodeout, *Q2, *tmp, *WfullT, *wvc, *vpd, *pod;
    cudaGetSymbolAddress((void**)&gi, g_gi);
    cudaGetSymbolAddress((void**)&h0, g_h0);
    cudaGetSymbolAddress((void**)&h1, g_h1);
    cudaGetSymbolAddress((void**)&hall, g_hall);
    cudaGetSymbolAddress((void**)&nodeout, g_nodeout);
    cudaGetSymbolAddress((void**)&Q2, g_Q2);
    cudaGetSymbolAddress((void**)&tmp, g_tmp);
    cudaGetSymbolAddress((void**)&WfullT, g_WfullT);
    cudaGetSymbolAddress((void**)&wvc, g_wvc);
    cudaGetSymbolAddress((void**)&vpd, g_vp);
    cudaGetSymbolAddress((void**)&pod, g_po);

    static int smem_set = 0;
    if (!smem_set) {
        cudaFuncSetAttribute(gru_persist, cudaFuncAttributeMaxDynamicSharedMemorySize,
                             160 * 260 * 4);
        smem_set = 1;
    }

    // weight prep (tiny); prep_wvc also resets the grid barrier
    prep_tmp<<<256, 256>>>(Wq, Wbil, tmp);
    prep_wfull<<<256, 256>>>(tmp, Wk, WfullT);
    prep_wvc<<<1, 256>>>(Wprj, Wv, wvc);
    init_h<<<RALL, 256>>>(node_hidden, ngh_hidden, h0);

    // hoisted input-side GRU GEMMs via tensor cores: gi = X @ Wih^T
    gemm_xw<<<dim3(6, 32), 256>>>(node_input, Wih_node, gi);
    gemm_xw<<<dim3(6, 512), 256>>>(ngh_input, Wih_ngh, gi + (size_t)4096 * 768);

    // entire recurrence in one persistent kernel
    gru_persist<<<NBLK, 256, 160 * 260 * 4>>>(gi, Whh_node, Whh_ngh,
                                              bih_node, bhh_node, bih_ngh, bhh_ngh,
                                              h0, h1, hall, nodeout);

    // attention
    sgemm128<<<dim3(2, 32), 256>>>(nodeout, WfullT, Q2, 4096, 256, 256);
    vproj_kernel<<<FLATR / 8, 256>>>(hall, wvc, vpd);
    attn_kernel<<<B_ * M_, 256>>>(Q2, hall, vpd, bbil, out + OFF_A, pod);

    finalize<<<(OFF_A + 255) / 256, 256>>>(pod, bprj, h0 /*T even -> final in h0*/, out);
}

// round 4
// speedup vs baseline: 4.3805x; 1.1956x over previous
#include <cuda_runtime.h>
#include <cuda_bf16.h>
#include <math.h>
#include <stdint.h>

// Problem dims
#define B_  64
#define N_  16
#define T_  64
#define D_  128
#define H_  256
#define M_  17          // N+1 slots
#define RALL 1088       // B + B*N batch rows
#define FLATR 69632     // RALL*T  (also B*M_*T_)
#define NBLK 136        // persistent GRU grid (8 j-tiles x 17 m-tiles)

// Output offsets (concat of: out(4096), node_hT(16384), ngh_hT(262144), A(4456448))
#define OFF_OUT 0
#define OFF_NHT 4096
#define OFF_GHT 20480
#define OFF_A   282624

// ---------------- device scratch (no runtime allocation allowed) ----------------
__device__ float g_gi[(size_t)FLATR * 768];      // precomputed x@Wih.T, [(r*T+t)*768+j]
__device__ float g_h0[RALL * H_];                // ping-pong hidden state
__device__ float g_h1[RALL * H_];
__device__ float g_hall[(size_t)FLATR * H_];     // kv layout [((b*17+m)*64+t)*256+h]
__device__ float g_Q2[(size_t)B_ * T_ * H_];
__device__ float g_tmp[H_ * H_];                 // Wq^T @ Wbil
__device__ float g_WfullT[H_ * H_];              // (Wq^T Wbil Wk) transposed
__device__ float g_wvc[H_];                      // Wprj @ Wv
__device__ float g_vp[8 * FLATR];                // per-jt partial hall.wvc
__device__ float g_po[B_ * M_ * T_];             // per-slot partial output
__device__ unsigned g_bar;                       // grid barrier counter

// ---------------- tf32 helpers ----------------
__device__ __forceinline__ uint32_t f2tf32(float f) {
    uint32_t o;
    asm("cvt.rna.tf32.f32 %0, %1;" : "=r"(o) : "f"(f));
    return o;
}

__device__ __forceinline__ void mma_tf32(float& d0, float& d1, float& d2, float& d3,
                                         uint32_t a0, uint32_t a1, uint32_t a2, uint32_t a3,
                                         uint32_t b0, uint32_t b1) {
    asm volatile(
        "mma.sync.aligned.m16n8k8.row.col.f32.tf32.tf32.f32 "
        "{%0,%1,%2,%3}, {%4,%5,%6,%7}, {%8,%9}, {%0,%1,%2,%3};\n"
        : "+f"(d0), "+f"(d1), "+f"(d2), "+f"(d3)
        : "r"(a0), "r"(a1), "r"(a2), "r"(a3), "r"(b0), "r"(b1));
}

// ---------------- prep kernels ----------------
__global__ void prep_tmp(const float* __restrict__ Wq, const float* __restrict__ Wbil,
                         float* __restrict__ tmp) {
    int k = blockIdx.x, c = threadIdx.x;
    float s = 0.f;
    for (int a = 0; a < H_; a++) s += Wq[a * H_ + k] * Wbil[a * H_ + c];
    tmp[k * H_ + c] = s;
}

__global__ void prep_wfull(const float* __restrict__ tmp, const float* __restrict__ Wk,
                           float* __restrict__ WfullT) {
    int k = blockIdx.x, hp = threadIdx.x;
    float s = 0.f;
    for (int c = 0; c < H_; c++) s += tmp[k * H_ + c] * Wk[c * H_ + hp];
    WfullT[hp * H_ + k] = s;
}

__global__ void prep_wvc(const float* __restrict__ Wprj, const float* __restrict__ Wv,
                         float* __restrict__ wvc) {
    int hp = threadIdx.x;
    float s = 0.f;
    for (int h = 0; h < H_; h++) s += Wprj[h] * Wv[h * H_ + hp];
    wvc[hp] = s;
    if (hp == 0) g_bar = 0;     // reset grid barrier every launch/replay
}

__global__ void init_h(const float* __restrict__ node_hidden,
                       const float* __restrict__ ngh_hidden,
                       float* __restrict__ h) {
    int row = blockIdx.x, u = threadIdx.x;
    float v = (row < B_) ? node_hidden[row * H_ + u]
                         : ngh_hidden[(row - B_) * H_ + u];
    h[row * H_ + u] = v;
}

// ---------------- tf32 tensor-core GEMM: C[M x 768] = X[M x 128] @ W[768 x 128]^T ----
__global__ __launch_bounds__(256) void gemm_xw(const float* __restrict__ X,
                                               const float* __restrict__ W,
                                               float* __restrict__ C) {
    __shared__ uint32_t As[128 * 68];
    __shared__ uint32_t Bs[128 * 68];
    int tid = threadIdx.x;
    int warp = tid >> 5, lane = tid & 31;
    int gr = lane >> 2, gc = lane & 3;
    int m0 = blockIdx.y * 128, n0 = blockIdx.x * 128;
    int wm = (warp >> 2) * 64, wn = (warp & 3) * 32;

    float acc[4][4][4] = {};

    for (int k0 = 0; k0 < 128; k0 += 64) {
        for (int i = tid; i < 2048; i += 256) {
            int r = i >> 4, c4 = (i & 15) * 4;
            float4 v = *(const float4*)(X + (size_t)(m0 + r) * 128 + k0 + c4);
            uint4 u = { f2tf32(v.x), f2tf32(v.y), f2tf32(v.z), f2tf32(v.w) };
            *(uint4*)(As + r * 68 + c4) = u;
        }
        for (int i = tid; i < 2048; i += 256) {
            int r = i >> 4, c4 = (i & 15) * 4;
            float4 v = *(const float4*)(W + (size_t)(n0 + r) * 128 + k0 + c4);
            uint4 u = { f2tf32(v.x), f2tf32(v.y), f2tf32(v.z), f2tf32(v.w) };
            *(uint4*)(Bs + r * 68 + c4) = u;
        }
        __syncthreads();

        #pragma unroll
        for (int kk = 0; kk < 8; kk++) {
            uint32_t a[4][4], b[4][2];
            #pragma unroll
            for (int mt = 0; mt < 4; mt++) {
                int r = wm + mt * 16 + gr;
                a[mt][0] = As[r * 68 + kk * 8 + gc];
                a[mt][1] = As[(r + 8) * 68 + kk * 8 + gc];
                a[mt][2] = As[r * 68 + kk * 8 + gc + 4];
                a[mt][3] = As[(r + 8) * 68 + kk * 8 + gc + 4];
            }
            #pragma unroll
            for (int nt = 0; nt < 4; nt++) {
                int n = wn + nt * 8 + gr;
                b[nt][0] = Bs[n * 68 + kk * 8 + gc];
                b[nt][1] = Bs[n * 68 + kk * 8 + gc + 4];
            }
            #pragma unroll
            for (int mt = 0; mt < 4; mt++)
                #pragma unroll
                for (int nt = 0; nt < 4; nt++)
                    mma_tf32(acc[mt][nt][0], acc[mt][nt][1], acc[mt][nt][2], acc[mt][nt][3],
                             a[mt][0], a[mt][1], a[mt][2], a[mt][3], b[nt][0], b[nt][1]);
        }
        __syncthreads();
    }

    #pragma unroll
    for (int mt = 0; mt < 4; mt++) {
        int r1 = m0 + wm + mt * 16 + gr;
        #pragma unroll
        for (int nt = 0; nt < 4; nt++) {
            int col = n0 + wn + nt * 8 + 2 * gc;
            float2 v0 = { acc[mt][nt][0], acc[mt][nt][1] };
            float2 v1 = { acc[mt][nt][2], acc[mt][nt][3] };
            *(float2*)(C + (size_t)r1 * 768 + col) = v0;
            *(float2*)(C + (size_t)(r1 + 8) * 768 + col) = v1;
        }
    }
}

// ---------------- persistent GRU: all 64 steps in one kernel ----------------
// grid NBLK=136: jt = bx&7 (32-unit tile), mt = bx>>3 (64-row tile).
// Whh slice in smem once. h carried in registers for own (row, j).
// gi[t+1] prefetched into registers during the barrier spin.
// Also emits vp partials (hall . wvc restricted to own 32 units).
__global__ __launch_bounds__(256, 1) void gru_persist(
    const float* __restrict__ gi,
    const float* __restrict__ Whh_node, const float* __restrict__ Whh_ngh,
    const float* __restrict__ bih_node, const float* __restrict__ bhh_node,
    const float* __restrict__ bih_ngh,  const float* __restrict__ bhh_ngh,
    const float* __restrict__ wvc,
    float* __restrict__ h0, float* __restrict__ h1,
    float* __restrict__ hall, float* __restrict__ vp_part)
{
    extern __shared__ uint32_t sh[];
    uint32_t* Ws = sh;                 // 96 x 260
    uint32_t* Hs = sh + 96 * 260;      // 64 x 260 (aliased as GH[64][100] post-mma)
    float* GH = (float*)Hs;

    int tid = threadIdx.x;
    int warp = tid >> 5, lane = tid & 31;
    int gr = lane >> 2, gc = lane & 3;
    int bx = blockIdx.x;
    int jt = bx & 7, mt = bx >> 3;
    int j0 = jt * 32, m0 = mt * 64;
    bool is_node = (mt == 0);
    const float* Whh = is_node ? Whh_node : Whh_ngh;
    int wm = (warp >> 2) * 32;         // 0 or 32
    int wn = (warp & 3) * 24;          // 0,24,48,72

    // ---- load weight slice once ----
    for (int i = tid; i < 96 * 64; i += 256) {
        int r = i >> 6, c4 = (i & 63) * 4;
        int g = r >> 5, uu = r & 31;
        float4 v = *(const float4*)(Whh + (size_t)(g * 256 + j0 + uu) * 256 + c4);
        uint4 u = { f2tf32(v.x), f2tf32(v.y), f2tf32(v.z), f2tf32(v.w) };
        *(uint4*)(Ws + r * 260 + c4) = u;
    }

    const float* bih = is_node ? bih_node : bih_ngh;
    const float* bhh = is_node ? bhh_node : bhh_ngh;
    int j = j0 + lane;
    float bir = bih[j], biz = bih[256 + j], bin = bih[512 + j];
    float bhr = bhh[j], bhz = bhh[256 + j], bhn = bhh[512 + j];
    float wv = wvc[j];

    // per-row precomputed bases and register-carried h
    size_t pre_gi[8], pre_hall[8], pre_vp[8], pre_h[8];
    float hreg[8];
    #pragma unroll
    for (int rr = 0; rr < 8; rr++) {
        int R = m0 + warp * 8 + rr;
        pre_gi[rr] = (size_t)R * 49152 + j;               // R*T*768 + j
        int b, m;
        if (R < B_) { b = R; m = 0; }
        else { int q = R - B_; b = q >> 4; m = (q & 15) + 1; }
        size_t hallrow0 = ((size_t)b * M_ + m) * 64;      // + t
        pre_hall[rr] = hallrow0 * 256 + j;                // + t*256
        pre_vp[rr]  = (size_t)jt * FLATR + hallrow0;      // + t
        pre_h[rr]   = (size_t)R * 256 + j;
        hreg[rr] = h0[pre_h[rr]];
    }
    __syncthreads();

    // gi prefetch registers for current step
    float p_ir[8], p_iz[8], p_in[8];
    #pragma unroll
    for (int rr = 0; rr < 8; rr++) {
        p_ir[rr] = __ldg(gi + pre_gi[rr]);
        p_iz[rr] = __ldg(gi + pre_gi[rr] + 256);
        p_in[rr] = __ldg(gi + pre_gi[rr] + 512);
    }

    for (int t = 0; t < T_; t++) {
        const float* hcur = (t & 1) ? h1 : h0;
        float* hnext = (t & 1) ? h0 : h1;

        // ---- stage h tile (L1-bypassed: cross-block data) ----
        for (int i = tid; i < 64 * 64; i += 256) {
            int r = i >> 6, c4 = (i & 63) * 4;
            float4 v = __ldcg((const float4*)(hcur + (size_t)(m0 + r) * 256 + c4));
            uint4 u = { f2tf32(v.x), f2tf32(v.y), f2tf32(v.z), f2tf32(v.w) };
            *(uint4*)(Hs + r * 260 + c4) = u;
        }
        __syncthreads();

        // ---- gh = h @ Whh_slice^T ----
        float acc[2][3][4] = {};
        #pragma unroll
        for (int kk = 0; kk < 32; kk++) {
            uint32_t a[2][4], b[3][2];
            #pragma unroll
            for (int mm = 0; mm < 2; mm++) {
                int r = wm + mm * 16 + gr;
                a[mm][0] = Hs[r * 260 + kk * 8 + gc];
                a[mm][1] = Hs[(r + 8) * 260 + kk * 8 + gc];
                a[mm][2] = Hs[r * 260 + kk * 8 + gc + 4];
                a[mm][3] = Hs[(r + 8) * 260 + kk * 8 + gc + 4];
            }
            #pragma unroll
            for (int nt = 0; nt < 3; nt++) {
                int n = wn + nt * 8 + gr;
                b[nt][0] = Ws[n * 260 + kk * 8 + gc];
                b[nt][1] = Ws[n * 260 + kk * 8 + gc + 4];
            }
            #pragma unroll
            for (int mm = 0; mm < 2; mm++)
                #pragma unroll
                for (int nt = 0; nt < 3; nt++)
                    mma_tf32(acc[mm][nt][0], acc[mm][nt][1], acc[mm][nt][2], acc[mm][nt][3],
                             a[mm][0], a[mm][1], a[mm][2], a[mm][3], b[nt][0], b[nt][1]);
        }
        __syncthreads();   // Hs consumed; safe to alias as GH

        #pragma unroll
        for (int mm = 0; mm < 2; mm++) {
            int r1 = wm + mm * 16 + gr;
            #pragma unroll
            for (int nt = 0; nt < 3; nt++) {
                int col = wn + nt * 8 + 2 * gc;
                GH[r1 * 100 + col]           = acc[mm][nt][0];
                GH[r1 * 100 + col + 1]       = acc[mm][nt][1];
                GH[(r1 + 8) * 100 + col]     = acc[mm][nt][2];
                GH[(r1 + 8) * 100 + col + 1] = acc[mm][nt][3];
            }
        }
        __syncthreads();

        // ---- gates: thread (warp, lane) -> unit j, rows warp*8..+7 ----
        #pragma unroll
        for (int rr = 0; rr < 8; rr++) {
            int row = warp * 8 + rr;
            float gir = p_ir[rr] + bir;
            float giz = p_iz[rr] + biz;
            float gin = p_in[rr] + bin;
            float ghr = GH[row * 100 + lane]      + bhr;
            float ghz = GH[row * 100 + 32 + lane] + bhz;
            float ghn = GH[row * 100 + 64 + lane] + bhn;
            float r = 1.f / (1.f + expf(-(gir + ghr)));
            float z = 1.f / (1.f + expf(-(giz + ghz)));
            float n = tanhf(gin + r * ghn);
            float hnew = (1.f - z) * n + z * hreg[rr];
            hreg[rr] = hnew;
            hnext[pre_h[rr]] = hnew;
            hall[pre_hall[rr] + (size_t)t * 256] = hnew;
            // vp partial: reduce hnew*wv over the warp's 32 units
            float pv = hnew * wv;
            #pragma unroll
            for (int o = 16; o; o >>= 1) pv += __shfl_xor_sync(0xffffffffu, pv, o);
            if (lane == 0) vp_part[pre_vp[rr] + t] = pv;
        }

        // ---- grid barrier with gi prefetch overlapped ----
        __threadfence();
        __syncthreads();
        if (tid == 0) atomicAdd(&g_bar, 1u);
        if (t + 1 < T_) {
            #pragma unroll
            for (int rr = 0; rr < 8; rr++) {
                p_ir[rr] = __ldg(gi + pre_gi[rr] + (size_t)(t + 1) * 768);
                p_iz[rr] = __ldg(gi + pre_gi[rr] + (size_t)(t + 1) * 768 + 256);
                p_in[rr] = __ldg(gi + pre_gi[rr] + (size_t)(t + 1) * 768 + 512);
            }
        }
        if (tid == 0) {
            unsigned target = (unsigned)NBLK * (t + 1);
            while (*(volatile unsigned*)&g_bar < target) { }
            __threadfence();
        }
        __syncthreads();
    }
}

// ---------------- Q2 GEMM (fp32, reads node rows directly from hall) ----------------
// C[4096 x 256] = nodeout @ WfullT^T ; nodeout row r -> hall row (r>>6)*1088 + (r&63)
__global__ __launch_bounds__(256) void sgemm_q2(const float* __restrict__ hall,
                                                const float* __restrict__ Bw,
                                                float* __restrict__ C) {
    __shared__ float As[8][128];
    __shared__ float Bs[8][128];
    int tid = threadIdx.x;
    int tx = tid & 15, ty = tid >> 4;
    int m0 = blockIdx.y * 128, n0 = blockIdx.x * 128;
    float acc[8][8] = {};
    for (int k0 = 0; k0 < 256; k0 += 8) {
        #pragma unroll
        for (int i = 0; i < 4; i++) {
            int idx = tid + i * 256;
            int r = idx >> 3, c = idx & 7;
            int row = m0 + r;
            size_t hrow = (size_t)(row >> 6) * 1088 + (row & 63);
            As[c][r] = hall[hrow * 256 + k0 + c];
            Bs[c][r] = Bw[(size_t)(n0 + r) * 256 + k0 + c];
        }
        __syncthreads();
        #pragma unroll
        for (int k = 0; k < 8; k++) {
            float a[8], bv[8];
            #pragma unroll
            for (int i = 0; i < 8; i++) a[i] = As[k][ty * 8 + i];
            #pragma unroll
            for (int jj = 0; jj < 8; jj++) bv[jj] = Bs[k][tx * 8 + jj];
            #pragma unroll
            for (int i = 0; i < 8; i++)
                #pragma unroll
                for (int jj = 0; jj < 8; jj++) acc[i][jj] += a[i] * bv[jj];
        }
        __syncthreads();
    }
    #pragma unroll
    for (int i = 0; i < 8; i++)
        #pragma unroll
        for (int jj = 0; jj < 8; jj++)
            C[(size_t)(m0 + ty * 8 + i) * 256 + n0 + tx * 8 + jj] = acc[i][jj];
}

// ---------------- fused attention: S -> mask -> softmax -> A out + A@vproj ----------------
__global__ __launch_bounds__(256) void attn_kernel(
    const float* __restrict__ Q2, const float* __restrict__ hall,
    const float* __restrict__ vp_part, const float* __restrict__ bbil,
    float* __restrict__ A_out, float* __restrict__ po)
{
    __shared__ float Qs[16][64];
    __shared__ float Ks[16][64];
    __shared__ float Ssm[64 * 65];
    __shared__ float vps[64];
    __shared__ float bb[64];

    int bm = blockIdx.x;
    int b = bm / M_;
    int tid = threadIdx.x;
    const float* qsrc = Q2 + (size_t)b * T_ * H_;
    const float* ksrc = hall + (size_t)bm * T_ * H_;
    if (tid < 64) {
        float s = 0.f;
        #pragma unroll
        for (int jt = 0; jt < 8; jt++) s += vp_part[(size_t)jt * FLATR + bm * 64 + tid];
        vps[tid] = s;
        bb[tid] = bbil[tid];
    }

    int tx = tid & 15, ty = tid >> 4;
    float acc[4][4] = {};
    for (int k0 = 0; k0 < H_; k0 += 16) {
        #pragma unroll
        for (int i = 0; i < 4; i++) {
            int idx = tid + i * 256;
            int r = idx >> 4, c = idx & 15;
            Qs[c][r] = qsrc[r * H_ + k0 + c];
            Ks[c][r] = ksrc[r * H_ + k0 + c];
        }
        __syncthreads();
        #pragma unroll
        for (int k = 0; k < 16; k++) {
            float q[4], kv[4];
            #pragma unroll
            for (int i = 0; i < 4; i++) q[i]  = Qs[k][ty + 16 * i];
            #pragma unroll
            for (int jj = 0; jj < 4; jj++) kv[jj] = Ks[k][tx + 16 * jj];
            #pragma unroll
            for (int i = 0; i < 4; i++)
                #pragma unroll
                for (int jj = 0; jj < 4; jj++) acc[i][jj] += q[i] * kv[jj];
        }
        __syncthreads();
    }
    #pragma unroll
    for (int i = 0; i < 4; i++)
        #pragma unroll
        for (int jj = 0; jj < 4; jj++)
            Ssm[(ty + 16 * i) * 65 + tx + 16 * jj] = acc[i][jj];
    __syncthreads();

    int warp = tid >> 5, lane = tid & 31;
    for (int rr = 0; rr < 8; rr++) {
        int t = warp * 8 + rr;
        int s2 = lane + 32;
        bool v1ok = (lane <= t), v2ok = (s2 <= t);
        float v1 = v1ok ? Ssm[t * 65 + lane] + bb[lane] : -3.0e38f;
        float v2 = v2ok ? Ssm[t * 65 + s2]   + bb[s2]   : -3.0e38f;
        float mx = fmaxf(v1, v2);
        #pragma unroll
        for (int o = 16; o; o >>= 1) mx = fmaxf(mx, __shfl_xor_sync(0xffffffffu, mx, o));
        float p1 = v1ok ? expf(v1 - mx) : 0.f;
        float p2 = v2ok ? expf(v2 - mx) : 0.f;
        float sum = p1 + p2;
        #pragma unroll
        for (int o = 16; o; o >>= 1) sum += __shfl_xor_sync(0xffffffffu, sum, o);
        float inv = 1.f / sum;
        float a1 = p1 * inv, a2 = p2 * inv;
        size_t abase = ((size_t)bm * 64 + t) * 64;
        A_out[abase + lane]      = a1;
        A_out[abase + lane + 32] = a2;
        float pv = a1 * vps[lane] + a2 * vps[s2];
        #pragma unroll
        for (int o = 16; o; o >>= 1) pv += __shfl_xor_sync(0xffffffffu, pv, o);
        if (lane == 0) po[bm * 64 + t] = pv;
    }
}

// ---------------- finalize: out reduce over slots + hT copies ----------------
__global__ void finalize(const float* __restrict__ po, const float* __restrict__ bprj,
                         const float* __restrict__ hfin, float* __restrict__ out) {
    int idx = blockIdx.x * 256 + threadIdx.x;
    if (idx < 4096) {
        int b = idx >> 6, t = idx & 63;
        float s = 17.f * bprj[0];
        #pragma unroll
        for (int m = 0; m < M_; m++) s += po[(b * M_ + m) * 64 + t];
        out[idx] = s;
    } else if (idx < OFF_GHT) {
        out[idx] = hfin[idx - OFF_NHT];               // node_hT
    } else if (idx < OFF_A) {
        out[idx] = hfin[B_ * H_ + (idx - OFF_GHT)];   // ngh_hT
    }
}

// ---------------- launch ----------------
extern "C" void kernel_launch(void* const* d_in, const int* in_sizes, int n_in,
                              void* d_out, int out_size) {
    const float* node_input   = (const float*)d_in[0];
    const float* node_hidden  = (const float*)d_in[1];
    const float* ngh_input    = (const float*)d_in[2];
    const float* ngh_hidden   = (const float*)d_in[3];
    // d_in[4] = s_len (unused by reference)
    const float* Wih_node = (const float*)d_in[5];
    const float* Whh_node = (const float*)d_in[6];
    const float* bih_node = (const float*)d_in[7];
    const float* bhh_node = (const float*)d_in[8];
    const float* Wih_ngh  = (const float*)d_in[9];
    const float* Whh_ngh  = (const float*)d_in[10];
    const float* bih_ngh  = (const float*)d_in[11];
    const float* bhh_ngh  = (const float*)d_in[12];
    const float* Wq   = (const float*)d_in[13];
    const float* Wk   = (const float*)d_in[14];
    const float* Wv   = (const float*)d_in[15];
    const float* Wbil = (const float*)d_in[16];
    const float* bbil = (const float*)d_in[17];
    const float* Wprj = (const float*)d_in[18];
    const float* bprj = (const float*)d_in[19];
    float* out = (float*)d_out;

    float *gi, *h0, *h1, *hall, *Q2, *tmp, *WfullT, *wvc, *vpd, *pod;
    cudaGetSymbolAddress((void**)&gi, g_gi);
    cudaGetSymbolAddress((void**)&h0, g_h0);
    cudaGetSymbolAddress((void**)&h1, g_h1);
    cudaGetSymbolAddress((void**)&hall, g_hall);
    cudaGetSymbolAddress((void**)&Q2, g_Q2);
    cudaGetSymbolAddress((void**)&tmp, g_tmp);
    cudaGetSymbolAddress((void**)&WfullT, g_WfullT);
    cudaGetSymbolAddress((void**)&wvc, g_wvc);
    cudaGetSymbolAddress((void**)&vpd, g_vp);
    cudaGetSymbolAddress((void**)&pod, g_po);

    static int smem_set = 0;
    if (!smem_set) {
        cudaFuncSetAttribute(gru_persist, cudaFuncAttributeMaxDynamicSharedMemorySize,
                             160 * 260 * 4);
        smem_set = 1;
    }

    // weight prep (tiny); prep_wvc also resets the grid barrier
    prep_tmp<<<256, 256>>>(Wq, Wbil, tmp);
    prep_wfull<<<256, 256>>>(tmp, Wk, WfullT);
    prep_wvc<<<1, 256>>>(Wprj, Wv, wvc);
    init_h<<<RALL, 256>>>(node_hidden, ngh_hidden, h0);

    // hoisted input-side GRU GEMMs via tensor cores: gi = X @ Wih^T
    gemm_xw<<<dim3(6, 32), 256>>>(node_input, Wih_node, gi);
    gemm_xw<<<dim3(6, 512), 256>>>(ngh_input, Wih_ngh, gi + (size_t)4096 * 768);

    // entire recurrence in one persistent kernel (also emits vp partials)
    gru_persist<<<NBLK, 256, 160 * 260 * 4>>>(gi, Whh_node, Whh_ngh,
                                              bih_node, bhh_node, bih_ngh, bhh_ngh,
                                              wvc, h0, h1, hall, vpd);

    // attention
    sgemm_q2<<<dim3(2, 32), 256>>>(hall, WfullT, Q2);
    attn_kernel<<<B_ * M_, 256>>>(Q2, hall, vpd, bbil, out + OFF_A, pod);

    finalize<<<(OFF_A + 255) / 256, 256>>>(pod, bprj, h0 /*T even -> final in h0*/, out);
}